// round 2
// baseline (speedup 1.0000x reference)
#include <cuda_runtime.h>
#include <cmath>

// Problem constants: B=16, C=64, H=W=256, bins=8, k=2
#define BC    1024          // B*C images
#define NJ    129           // Hermitian columns 0..128
#define NBINS 8

// Scratch: row-FFT results, layout [bc][j][i], i contiguous (coalesced pass-2 reads)
__device__ float2 g_scratch[(size_t)BC * NJ * 256];   // ~258 MB
// Per-(bc,j) binned partial sums (deterministic, no atomics)
__device__ float  g_partial[(size_t)BC * NJ * NBINS]; // ~4.2 MB

__device__ __forceinline__ float2 cmul(float2 a, float2 b) {
    return make_float2(fmaf(a.x, b.x, -a.y * b.y), fmaf(a.x, b.y, a.y * b.x));
}

// ---------------------------------------------------------------------------
// Pass 1: row FFTs. One block = 16 rows of one image = 8 complex FFTs
// (two real rows packed per complex FFT). Stockham radix-2, 8 stages.
// Writes Hermitian-half columns transposed into g_scratch (coalesced along i).
// ---------------------------------------------------------------------------
__global__ void __launch_bounds__(256) rowfft_kernel(const float* __restrict__ x) {
    __shared__ float2 bufA[8 * 256];
    __shared__ float2 bufB[8 * 256];
    __shared__ float2 tw[128];

    const int t  = threadIdx.x;
    const int bc = blockIdx.x >> 4;
    const int i0 = (blockIdx.x & 15) << 4;

    if (t < 128) {
        float s, c;
        sincosf(6.28318530717958647692f * ((float)t / 256.0f), &s, &c);
        tw[t] = make_float2(c, -s);   // W_256^t = exp(-2*pi*i*t/256)
    }

    const float scale = 1.0f / 65536.0f;   // norm='forward'
    const float* base = x + ((size_t)bc * 256 + i0) * 256;

    // Pack rows (2r, 2r+1) as one complex row; coalesced reads
    #pragma unroll
    for (int it = 0; it < 8; it++) {
        int r = it;          // complex-FFT id 0..7
        int n = t;           // column 0..255
        bufA[r * 256 + n] = make_float2(base[(size_t)(2 * r) * 256 + n] * scale,
                                        base[(size_t)(2 * r + 1) * 256 + n] * scale);
    }
    __syncthreads();

    // 8-stage Stockham DIF, natural-order output. 8 FFTs x 128 bflies / stage.
    float2* in  = bufA;
    float2* out = bufB;
    int nn = 256, ls = 0;
    #pragma unroll
    for (int stage = 0; stage < 8; stage++) {
        const int m   = nn >> 1;
        const int twm = 256 / nn;
        #pragma unroll
        for (int it = 0; it < 4; it++) {
            int gu = t + it * 256;        // 0..1023
            int f  = gu >> 7;             // FFT id
            int u  = gu & 127;            // butterfly id
            int q  = u & ((1 << ls) - 1);
            int p  = u >> ls;
            float2 a = in[f * 256 + q + (p << ls)];
            float2 b = in[f * 256 + q + ((p + m) << ls)];
            float2 w = tw[p * twm];
            out[f * 256 + q + ((2 * p) << ls)]     = make_float2(a.x + b.x, a.y + b.y);
            float2 d0 = make_float2(a.x - b.x, a.y - b.y);
            out[f * 256 + q + ((2 * p + 1) << ls)] = cmul(d0, w);
        }
        __syncthreads();
        float2* tmp = in; in = out; out = tmp;
        nn >>= 1; ls++;
    }

    // Conjugate untangle: A[j]=0.5(Z[j]+conj(Z[-j])), B[j]=-0.5i(Z[j]-conj(Z[-j]))
    // Write transposed: scratch[bc][j][i0+rr], 16 consecutive i per j -> 128B segs
    float2* Z = in;
    for (int idx = t; idx < NJ * 16; idx += 256) {
        int j  = idx >> 4;
        int rr = idx & 15;
        int r  = rr >> 1;
        float2 zj = Z[r * 256 + j];
        float2 zm = Z[r * 256 + ((256 - j) & 255)];
        float2 v;
        if ((rr & 1) == 0)
            v = make_float2(0.5f * (zj.x + zm.x), 0.5f * (zj.y - zm.y));
        else
            v = make_float2(0.5f * (zj.y + zm.y), -0.5f * (zj.x - zm.x));
        g_scratch[((size_t)bc * NJ + j) * 256 + i0 + rr] = v;
    }
}

// ---------------------------------------------------------------------------
// Pass 2: column FFTs + magnitude + radial binning.
// One block (128 thr) per (bc, j). Column weight 2 for j=1..127 (Hermitian
// mirror), 1 for j=0,128. Deterministic per-block reduction -> g_partial.
// ---------------------------------------------------------------------------
__global__ void __launch_bounds__(128) colfft_kernel() {
    __shared__ float2 bufA[256];
    __shared__ float2 bufB[256];
    __shared__ float2 tw[128];
    __shared__ float  warpred[4 * NBINS];

    const int t  = threadIdx.x;
    const int bc = blockIdx.x / NJ;
    const int j  = blockIdx.x - bc * NJ;

    {
        float s, c;
        sincosf(6.28318530717958647692f * ((float)t / 256.0f), &s, &c);
        tw[t] = make_float2(c, -s);
    }
    const float2* src = g_scratch + ((size_t)bc * NJ + j) * 256;
    bufA[t]       = src[t];
    bufA[t + 128] = src[t + 128];
    __syncthreads();

    float2* in  = bufA;
    float2* out = bufB;
    int nn = 256, ls = 0;
    #pragma unroll
    for (int stage = 0; stage < 8; stage++) {
        const int m   = nn >> 1;
        const int twm = 256 / nn;
        int q = t & ((1 << ls) - 1);
        int p = t >> ls;
        float2 a = in[q + (p << ls)];
        float2 b = in[q + ((p + m) << ls)];
        float2 w = tw[p * twm];
        out[q + ((2 * p) << ls)]     = make_float2(a.x + b.x, a.y + b.y);
        float2 d0 = make_float2(a.x - b.x, a.y - b.y);
        out[q + ((2 * p + 1) << ls)] = cmul(d0, w);
        __syncthreads();
        float2* tmp = in; in = out; out = tmp;
        nn >>= 1; ls++;
    }

    // magnitudes + exact searchsorted-right binning
    const float xj  = (float)(j - 128);
    const float xj2 = xj * xj;
    const float step = sqrtf(32768.0f) * 0.125f;  // dmax/8, exact /8
    float bins[NBINS];
    #pragma unroll
    for (int k = 0; k < NBINS; k++) bins[k] = 0.0f;

    #pragma unroll
    for (int half = 0; half < 2; half++) {
        int i = t + half * 128;
        float2 v = in[i];
        float mag = sqrtf(v.x * v.x + v.y * v.y);
        float yy = (float)(i - 128);
        float d  = __fsqrt_rn(yy * yy + xj2);   // exact integer radicand -> RN sqrt
        int b = 0;
        #pragma unroll
        for (int k = 1; k <= 8; k++) {
            if ((float)k * step <= d) b = k;    // searchsorted 'right' - 1
        }
        // b == 8 (d == dmax) is dropped by onehot[:, :8]
        #pragma unroll
        for (int k = 0; k < NBINS; k++) bins[k] += (b == k) ? mag : 0.0f;
    }

    // warp shuffle reduce (deterministic), then 4-warp combine
    #pragma unroll
    for (int k = 0; k < NBINS; k++) {
        #pragma unroll
        for (int o = 16; o > 0; o >>= 1)
            bins[k] += __shfl_xor_sync(0xffffffffu, bins[k], o);
    }
    const int lane = t & 31, w = t >> 5;
    if (lane == 0) {
        #pragma unroll
        for (int k = 0; k < NBINS; k++) warpred[w * NBINS + k] = bins[k];
    }
    __syncthreads();
    if (t < NBINS) {
        float s = warpred[t] + warpred[NBINS + t] + warpred[2 * NBINS + t] + warpred[3 * NBINS + t];
        float mj = (j == 0 || j == 128) ? 1.0f : 2.0f;
        g_partial[((size_t)bc * NJ + j) * NBINS + t] = s * mj;
    }
}

// ---------------------------------------------------------------------------
// Pass 3: per-batch reduce over (c, j), mean over C, MLP + softmax + top-2.
// Output layout: out[0..31] = topk_idx (as float, [16,2]), out[32..63] = topk_w.
// ---------------------------------------------------------------------------
__global__ void __launch_bounds__(256) finalize_kernel(
    const float* __restrict__ W1, const float* __restrict__ b1,
    const float* __restrict__ W2, const float* __restrict__ b2,
    float* __restrict__ outp, int out_size) {
    __shared__ float red[8 * NBINS];
    const int b = blockIdx.x;
    const int t = threadIdx.x;
    const float* base = g_partial + (size_t)b * 64 * NJ * NBINS;

    float bins[NBINS];
    #pragma unroll
    for (int k = 0; k < NBINS; k++) bins[k] = 0.0f;
    const int NU = 64 * NJ;   // 8256 groups of 8
    for (int u = t; u < NU; u += 256) {
        const float4* p4 = (const float4*)(base + (size_t)u * NBINS);
        float4 lo = p4[0], hi = p4[1];
        bins[0] += lo.x; bins[1] += lo.y; bins[2] += lo.z; bins[3] += lo.w;
        bins[4] += hi.x; bins[5] += hi.y; bins[6] += hi.z; bins[7] += hi.w;
    }
    #pragma unroll
    for (int k = 0; k < NBINS; k++) {
        #pragma unroll
        for (int o = 16; o > 0; o >>= 1)
            bins[k] += __shfl_xor_sync(0xffffffffu, bins[k], o);
    }
    const int lane = t & 31, w = t >> 5;
    if (lane == 0) {
        #pragma unroll
        for (int k = 0; k < NBINS; k++) red[w * NBINS + k] = bins[k];
    }
    __syncthreads();

    if (t == 0) {
        float e[NBINS];
        #pragma unroll
        for (int k = 0; k < NBINS; k++) {
            float s = 0.0f;
            #pragma unroll
            for (int ww = 0; ww < 8; ww++) s += red[ww * NBINS + k];
            e[k] = s * (1.0f / 64.0f);   // mean over C
        }
        // h = relu(e @ W1.T + b1)  [32]
        float h[32];
        #pragma unroll
        for (int m = 0; m < 32; m++) {
            float acc = b1[m];
            #pragma unroll
            for (int k = 0; k < NBINS; k++) acc = fmaf(e[k], W1[m * NBINS + k], acc);
            h[m] = acc > 0.0f ? acc : 0.0f;
        }
        // logits = h @ W2.T + b2  [4]
        float lg[4];
        #pragma unroll
        for (int o = 0; o < 4; o++) {
            float acc = b2[o];
            #pragma unroll
            for (int m = 0; m < 32; m++) acc = fmaf(h[m], W2[o * 32 + m], acc);
            lg[o] = acc;
        }
        float mx = lg[0];
        #pragma unroll
        for (int o = 1; o < 4; o++) mx = fmaxf(mx, lg[o]);
        float ex[4], se = 0.0f;
        #pragma unroll
        for (int o = 0; o < 4; o++) { ex[o] = expf(lg[o] - mx); se += ex[o]; }
        float pr[4];
        #pragma unroll
        for (int o = 0; o < 4; o++) pr[o] = ex[o] / se;

        // top-2 (ties -> lowest index first, matching lax.top_k)
        int i1 = 0;
        #pragma unroll
        for (int o = 1; o < 4; o++) if (pr[o] > pr[i1]) i1 = o;
        int i2 = -1;
        #pragma unroll
        for (int o = 0; o < 4; o++) {
            if (o == i1) continue;
            if (i2 < 0 || pr[o] > pr[i2]) i2 = o;
        }
        // softmax over the two top probs
        float p1 = pr[i1], p2 = pr[i2];
        float q2 = expf(p2 - p1);
        float w1v = 1.0f / (1.0f + q2);
        float w2v = q2 / (1.0f + q2);

        int o0 = b * 2, o1 = b * 2 + 1;
        if (o0 < out_size) outp[o0] = (float)i1;
        if (o1 < out_size) outp[o1] = (float)i2;
        if (32 + o0 < out_size) outp[32 + o0] = w1v;
        if (32 + o1 < out_size) outp[32 + o1] = w2v;
    }
}

// ---------------------------------------------------------------------------
extern "C" void kernel_launch(void* const* d_in, const int* in_sizes, int n_in,
                              void* d_out, int out_size) {
    const float* x  = (const float*)d_in[0];   // [16,64,256,256]
    const float* W1 = (const float*)d_in[1];   // [32,8]
    const float* b1 = (const float*)d_in[2];   // [32]
    const float* W2 = (const float*)d_in[3];   // [4,32]
    const float* b2 = (const float*)d_in[4];   // [4]
    // d_in[5] = k (int32), fixed at 2

    rowfft_kernel<<<BC * 16, 256>>>(x);
    colfft_kernel<<<BC * NJ, 128>>>();
    finalize_kernel<<<16, 256>>>(W1, b1, W2, b2, (float*)d_out, out_size);
}

// round 3
// speedup vs baseline: 1.0003x; 1.0003x over previous
#include <cuda_runtime.h>
#include <cmath>

// Problem constants: B=16, C=64, H=W=256, bins=8, k=2
#define BC    1024          // B*C images
#define NJ    129           // Hermitian columns 0..128
#define NBINS 8

// Scratch: row-FFT results, layout [bc][j][i], i contiguous (coalesced pass-2 reads)
__device__ float2 g_scratch[(size_t)BC * NJ * 256];   // ~258 MB
// Per-(bc,j) binned partial sums (deterministic, no atomics)
__device__ float  g_partial[(size_t)BC * NJ * NBINS]; // ~4.2 MB

__device__ __forceinline__ float2 cmul(float2 a, float2 b) {
    return make_float2(fmaf(a.x, b.x, -a.y * b.y), fmaf(a.x, b.y, a.y * b.x));
}

// ---------------------------------------------------------------------------
// Pass 1: row FFTs. One block = 16 rows of one image = 8 complex FFTs
// (two real rows packed per complex FFT). Stockham radix-2, 8 stages.
// Writes Hermitian-half columns transposed into g_scratch (coalesced along i).
// ---------------------------------------------------------------------------
__global__ void __launch_bounds__(256) rowfft_kernel(const float* __restrict__ x) {
    __shared__ float2 bufA[8 * 256];
    __shared__ float2 bufB[8 * 256];
    __shared__ float2 tw[128];

    const int t  = threadIdx.x;
    const int bc = blockIdx.x >> 4;
    const int i0 = (blockIdx.x & 15) << 4;

    if (t < 128) {
        float s, c;
        sincosf(6.28318530717958647692f * ((float)t / 256.0f), &s, &c);
        tw[t] = make_float2(c, -s);   // W_256^t = exp(-2*pi*i*t/256)
    }

    const float scale = 1.0f / 65536.0f;   // norm='forward'
    const float* base = x + ((size_t)bc * 256 + i0) * 256;

    // Pack rows (2r, 2r+1) as one complex row; coalesced reads
    #pragma unroll
    for (int it = 0; it < 8; it++) {
        int r = it;          // complex-FFT id 0..7
        int n = t;           // column 0..255
        bufA[r * 256 + n] = make_float2(base[(size_t)(2 * r) * 256 + n] * scale,
                                        base[(size_t)(2 * r + 1) * 256 + n] * scale);
    }
    __syncthreads();

    // 8-stage Stockham DIF, natural-order output. 8 FFTs x 128 bflies / stage.
    float2* in  = bufA;
    float2* out = bufB;
    int nn = 256, ls = 0;
    #pragma unroll
    for (int stage = 0; stage < 8; stage++) {
        const int m   = nn >> 1;
        const int twm = 256 / nn;
        #pragma unroll
        for (int it = 0; it < 4; it++) {
            int gu = t + it * 256;        // 0..1023
            int f  = gu >> 7;             // FFT id
            int u  = gu & 127;            // butterfly id
            int q  = u & ((1 << ls) - 1);
            int p  = u >> ls;
            float2 a = in[f * 256 + q + (p << ls)];
            float2 b = in[f * 256 + q + ((p + m) << ls)];
            float2 w = tw[p * twm];
            out[f * 256 + q + ((2 * p) << ls)]     = make_float2(a.x + b.x, a.y + b.y);
            float2 d0 = make_float2(a.x - b.x, a.y - b.y);
            out[f * 256 + q + ((2 * p + 1) << ls)] = cmul(d0, w);
        }
        __syncthreads();
        float2* tmp = in; in = out; out = tmp;
        nn >>= 1; ls++;
    }

    // Conjugate untangle: A[j]=0.5(Z[j]+conj(Z[-j])), B[j]=-0.5i(Z[j]-conj(Z[-j]))
    // Write transposed: scratch[bc][j][i0+rr], 16 consecutive i per j -> 128B segs
    float2* Z = in;
    for (int idx = t; idx < NJ * 16; idx += 256) {
        int j  = idx >> 4;
        int rr = idx & 15;
        int r  = rr >> 1;
        float2 zj = Z[r * 256 + j];
        float2 zm = Z[r * 256 + ((256 - j) & 255)];
        float2 v;
        if ((rr & 1) == 0)
            v = make_float2(0.5f * (zj.x + zm.x), 0.5f * (zj.y - zm.y));
        else
            v = make_float2(0.5f * (zj.y + zm.y), -0.5f * (zj.x - zm.x));
        g_scratch[((size_t)bc * NJ + j) * 256 + i0 + rr] = v;
    }
}

// ---------------------------------------------------------------------------
// Pass 2: column FFTs + magnitude + radial binning.
// One block (128 thr) per (bc, j). Column weight 2 for j=1..127 (Hermitian
// mirror), 1 for j=0,128. Deterministic per-block reduction -> g_partial.
// ---------------------------------------------------------------------------
__global__ void __launch_bounds__(128) colfft_kernel() {
    __shared__ float2 bufA[256];
    __shared__ float2 bufB[256];
    __shared__ float2 tw[128];
    __shared__ float  warpred[4 * NBINS];

    const int t  = threadIdx.x;
    const int bc = blockIdx.x / NJ;
    const int j  = blockIdx.x - bc * NJ;

    {
        float s, c;
        sincosf(6.28318530717958647692f * ((float)t / 256.0f), &s, &c);
        tw[t] = make_float2(c, -s);
    }
    const float2* src = g_scratch + ((size_t)bc * NJ + j) * 256;
    bufA[t]       = src[t];
    bufA[t + 128] = src[t + 128];
    __syncthreads();

    float2* in  = bufA;
    float2* out = bufB;
    int nn = 256, ls = 0;
    #pragma unroll
    for (int stage = 0; stage < 8; stage++) {
        const int m   = nn >> 1;
        const int twm = 256 / nn;
        int q = t & ((1 << ls) - 1);
        int p = t >> ls;
        float2 a = in[q + (p << ls)];
        float2 b = in[q + ((p + m) << ls)];
        float2 w = tw[p * twm];
        out[q + ((2 * p) << ls)]     = make_float2(a.x + b.x, a.y + b.y);
        float2 d0 = make_float2(a.x - b.x, a.y - b.y);
        out[q + ((2 * p + 1) << ls)] = cmul(d0, w);
        __syncthreads();
        float2* tmp = in; in = out; out = tmp;
        nn >>= 1; ls++;
    }

    // magnitudes + exact searchsorted-right binning
    const float xj  = (float)(j - 128);
    const float xj2 = xj * xj;
    const float step = sqrtf(32768.0f) * 0.125f;  // dmax/8, exact /8
    float bins[NBINS];
    #pragma unroll
    for (int k = 0; k < NBINS; k++) bins[k] = 0.0f;

    #pragma unroll
    for (int half = 0; half < 2; half++) {
        int i = t + half * 128;
        float2 v = in[i];
        float mag = sqrtf(v.x * v.x + v.y * v.y);
        float yy = (float)(i - 128);
        float d  = __fsqrt_rn(yy * yy + xj2);   // exact integer radicand -> RN sqrt
        int b = 0;
        #pragma unroll
        for (int k = 1; k <= 8; k++) {
            if ((float)k * step <= d) b = k;    // searchsorted 'right' - 1
        }
        // b == 8 (d == dmax) is dropped by onehot[:, :8]
        #pragma unroll
        for (int k = 0; k < NBINS; k++) bins[k] += (b == k) ? mag : 0.0f;
    }

    // warp shuffle reduce (deterministic), then 4-warp combine
    #pragma unroll
    for (int k = 0; k < NBINS; k++) {
        #pragma unroll
        for (int o = 16; o > 0; o >>= 1)
            bins[k] += __shfl_xor_sync(0xffffffffu, bins[k], o);
    }
    const int lane = t & 31, w = t >> 5;
    if (lane == 0) {
        #pragma unroll
        for (int k = 0; k < NBINS; k++) warpred[w * NBINS + k] = bins[k];
    }
    __syncthreads();
    if (t < NBINS) {
        float s = warpred[t] + warpred[NBINS + t] + warpred[2 * NBINS + t] + warpred[3 * NBINS + t];
        float mj = (j == 0 || j == 128) ? 1.0f : 2.0f;
        g_partial[((size_t)bc * NJ + j) * NBINS + t] = s * mj;
    }
}

// ---------------------------------------------------------------------------
// Pass 3: per-batch reduce over (c, j), mean over C, MLP + softmax + top-2.
// Output layout: out[0..31] = topk_idx (as float, [16,2]), out[32..63] = topk_w.
// ---------------------------------------------------------------------------
__global__ void __launch_bounds__(256) finalize_kernel(
    const float* __restrict__ W1, const float* __restrict__ b1,
    const float* __restrict__ W2, const float* __restrict__ b2,
    float* __restrict__ outp, int out_size) {
    __shared__ float red[8 * NBINS];
    const int b = blockIdx.x;
    const int t = threadIdx.x;
    const float* base = g_partial + (size_t)b * 64 * NJ * NBINS;

    float bins[NBINS];
    #pragma unroll
    for (int k = 0; k < NBINS; k++) bins[k] = 0.0f;
    const int NU = 64 * NJ;   // 8256 groups of 8
    for (int u = t; u < NU; u += 256) {
        const float4* p4 = (const float4*)(base + (size_t)u * NBINS);
        float4 lo = p4[0], hi = p4[1];
        bins[0] += lo.x; bins[1] += lo.y; bins[2] += lo.z; bins[3] += lo.w;
        bins[4] += hi.x; bins[5] += hi.y; bins[6] += hi.z; bins[7] += hi.w;
    }
    #pragma unroll
    for (int k = 0; k < NBINS; k++) {
        #pragma unroll
        for (int o = 16; o > 0; o >>= 1)
            bins[k] += __shfl_xor_sync(0xffffffffu, bins[k], o);
    }
    const int lane = t & 31, w = t >> 5;
    if (lane == 0) {
        #pragma unroll
        for (int k = 0; k < NBINS; k++) red[w * NBINS + k] = bins[k];
    }
    __syncthreads();

    if (t == 0) {
        float e[NBINS];
        #pragma unroll
        for (int k = 0; k < NBINS; k++) {
            float s = 0.0f;
            #pragma unroll
            for (int ww = 0; ww < 8; ww++) s += red[ww * NBINS + k];
            e[k] = s * (1.0f / 64.0f);   // mean over C
        }
        // h = relu(e @ W1.T + b1)  [32]
        float h[32];
        #pragma unroll
        for (int m = 0; m < 32; m++) {
            float acc = b1[m];
            #pragma unroll
            for (int k = 0; k < NBINS; k++) acc = fmaf(e[k], W1[m * NBINS + k], acc);
            h[m] = acc > 0.0f ? acc : 0.0f;
        }
        // logits = h @ W2.T + b2  [4]
        float lg[4];
        #pragma unroll
        for (int o = 0; o < 4; o++) {
            float acc = b2[o];
            #pragma unroll
            for (int m = 0; m < 32; m++) acc = fmaf(h[m], W2[o * 32 + m], acc);
            lg[o] = acc;
        }
        float mx = lg[0];
        #pragma unroll
        for (int o = 1; o < 4; o++) mx = fmaxf(mx, lg[o]);
        float ex[4], se = 0.0f;
        #pragma unroll
        for (int o = 0; o < 4; o++) { ex[o] = expf(lg[o] - mx); se += ex[o]; }
        float pr[4];
        #pragma unroll
        for (int o = 0; o < 4; o++) pr[o] = ex[o] / se;

        // top-2 (ties -> lowest index first, matching lax.top_k)
        int i1 = 0;
        #pragma unroll
        for (int o = 1; o < 4; o++) if (pr[o] > pr[i1]) i1 = o;
        int i2 = -1;
        #pragma unroll
        for (int o = 0; o < 4; o++) {
            if (o == i1) continue;
            if (i2 < 0 || pr[o] > pr[i2]) i2 = o;
        }
        // softmax over the two top probs
        float p1 = pr[i1], p2 = pr[i2];
        float q2 = expf(p2 - p1);
        float w1v = 1.0f / (1.0f + q2);
        float w2v = q2 / (1.0f + q2);

        int o0 = b * 2, o1 = b * 2 + 1;
        if (o0 < out_size) outp[o0] = (float)i1;
        if (o1 < out_size) outp[o1] = (float)i2;
        if (32 + o0 < out_size) outp[32 + o0] = w1v;
        if (32 + o1 < out_size) outp[32 + o1] = w2v;
    }
}

// ---------------------------------------------------------------------------
extern "C" void kernel_launch(void* const* d_in, const int* in_sizes, int n_in,
                              void* d_out, int out_size) {
    const float* x  = (const float*)d_in[0];   // [16,64,256,256]
    const float* W1 = (const float*)d_in[1];   // [32,8]
    const float* b1 = (const float*)d_in[2];   // [32]
    const float* W2 = (const float*)d_in[3];   // [4,32]
    const float* b2 = (const float*)d_in[4];   // [4]
    // d_in[5] = k (int32), fixed at 2

    rowfft_kernel<<<BC * 16, 256>>>(x);
    colfft_kernel<<<BC * NJ, 128>>>();
    finalize_kernel<<<16, 256>>>(W1, b1, W2, b2, (float*)d_out, out_size);
}

// round 4
// speedup vs baseline: 2.5790x; 2.5781x over previous
#include <cuda_runtime.h>
#include <cmath>

// Problem constants: B=16, C=64, H=W=256, bins=8, k=2
#define BC    1024
#define NJ    129
#define NBINS 8
#define PSTR  273   // per-FFT smem stride in float2 (16*17 + 1)

__device__ float2        g_scratch[(size_t)BC * NJ * 256];   // row-FFT halves, [bc][j][i]
__device__ float         g_partial[(size_t)BC * NJ * NBINS];
__device__ unsigned char g_bintab[NJ * 256];

__device__ __forceinline__ float2 cmul(float2 a, float2 b) {
    return make_float2(fmaf(a.x, b.x, -a.y * b.y), fmaf(a.x, b.y, a.y * b.x));
}
__device__ __forceinline__ float2 cadd(float2 a, float2 b) { return make_float2(a.x + b.x, a.y + b.y); }
__device__ __forceinline__ float2 csub(float2 a, float2 b) { return make_float2(a.x - b.x, a.y - b.y); }
__device__ __forceinline__ float2 mul_negi(float2 a) { return make_float2(a.y, -a.x); }

#define C16 0.92387953251128675613f
#define S16 0.38268343236508977173f
#define R22 0.70710678118654752440f

// 16-point forward DFT, natural order in/out, registers only.
// Decomposition 16 = 4x4: n = n1 + 4 n2, k = 4 k1 + k0.
__device__ __forceinline__ void fft16(float2 z[16]) {
    float2 y[16];
    #pragma unroll
    for (int n1 = 0; n1 < 4; n1++) {
        float2 a = z[n1], b = z[n1 + 4], c = z[n1 + 8], d = z[n1 + 12];
        float2 t0 = cadd(a, c), t1 = csub(a, c);
        float2 t2 = cadd(b, d), t3 = csub(b, d);
        float2 X0 = cadd(t0, t2);
        float2 X2 = csub(t0, t2);
        float2 X1 = make_float2(t1.x + t3.y, t1.y - t3.x);   // t1 - i t3
        float2 X3 = make_float2(t1.x - t3.y, t1.y + t3.x);   // t1 + i t3
        y[n1] = X0;
        if (n1 == 0) {
            y[4] = X1; y[8] = X2; y[12] = X3;
        } else if (n1 == 1) {
            y[5]  = cmul(X1, make_float2(C16, -S16));   // W16^1
            y[9]  = cmul(X2, make_float2(R22, -R22));   // W16^2
            y[13] = cmul(X3, make_float2(S16, -C16));   // W16^3
        } else if (n1 == 2) {
            y[6]  = cmul(X1, make_float2(R22, -R22));   // W16^2
            y[10] = mul_negi(X2);                       // W16^4
            y[14] = cmul(X3, make_float2(-R22, -R22));  // W16^6
        } else {
            y[7]  = cmul(X1, make_float2(S16, -C16));   // W16^3
            y[11] = cmul(X2, make_float2(-R22, -R22));  // W16^6
            y[15] = cmul(X3, make_float2(-C16,  S16));  // W16^9
        }
    }
    #pragma unroll
    for (int k0 = 0; k0 < 4; k0++) {
        float2 a = y[4 * k0], b = y[4 * k0 + 1], c = y[4 * k0 + 2], d = y[4 * k0 + 3];
        float2 t0 = cadd(a, c), t1 = csub(a, c);
        float2 t2 = cadd(b, d), t3 = csub(b, d);
        z[k0]      = cadd(t0, t2);
        z[k0 + 8]  = csub(t0, t2);
        z[k0 + 4]  = make_float2(t1.x + t3.y, t1.y - t3.x);
        z[k0 + 12] = make_float2(t1.x - t3.y, t1.y + t3.x);
    }
}

// 256-pt FFT core: thread (fl, r) with data staged in smem at s[fl*PSTR + idx17(n)],
// idx17(n) = n + (n>>4). On exit z[k1] = X[16*k1 + r] (r plays k2).
__device__ __forceinline__ void fft256_core(float2* __restrict__ s, int fl, int r, float2 z[16]) {
    #pragma unroll
    for (int n2 = 0; n2 < 16; n2++)
        z[n2] = s[fl * PSTR + 17 * n2 + r];
    fft16(z);                       // over n2 -> k2
    {
        float sn, cs;
        sincosf(0.02454369260617025967f * (float)r, &sn, &cs);  // 2*pi*n1/256
        float2 w1 = make_float2(cs, -sn);
        float2 w = w1;
        #pragma unroll
        for (int k2 = 1; k2 < 16; k2++) {
            z[k2] = cmul(z[k2], w);
            w = cmul(w, w1);
        }
    }
    __syncthreads();
    #pragma unroll
    for (int k2 = 0; k2 < 16; k2++)
        s[fl * PSTR + 17 * k2 + r] = z[k2];   // transpose
    __syncthreads();
    #pragma unroll
    for (int n1 = 0; n1 < 16; n1++)
        z[n1] = s[fl * PSTR + 17 * r + n1];
    fft16(z);                       // over n1 -> k1
}

// ---------------------------------------------------------------------------
// Bin table: exact replica of reference searchsorted-'right' semantics.
// ---------------------------------------------------------------------------
__global__ void bintab_kernel() {
    int j = blockIdx.x;
    int i = threadIdx.x;
    float xj = (float)(j - 128);
    float yy = (float)(i - 128);
    float d = __fsqrt_rn(yy * yy + xj * xj);
    const float step = sqrtf(32768.0f) * 0.125f;
    int b = 0;
    #pragma unroll
    for (int k = 1; k <= 8; k++)
        if ((float)k * step <= d) b = k;
    g_bintab[j * 256 + i] = (unsigned char)b;
}

// ---------------------------------------------------------------------------
// Pass 1: row FFTs. 128 threads = 8 complex FFTs (16 real rows, packed pairs).
// ---------------------------------------------------------------------------
__global__ void __launch_bounds__(128) rowfft_kernel(const float* __restrict__ x) {
    __shared__ float2 s[8 * PSTR];

    const int t  = threadIdx.x;
    const int bc = blockIdx.x >> 4;
    const int i0 = (blockIdx.x & 15) << 4;
    const float scale = 1.0f / 65536.0f;
    const float* base = x + ((size_t)bc * 256 + i0) * 256;

    // Phase A: stage 16 rows as 8 complex rows (coalesced loads)
    #pragma unroll
    for (int f = 0; f < 8; f++) {
        #pragma unroll
        for (int h = 0; h < 2; h++) {
            int n = t + 128 * h;
            s[f * PSTR + n + (n >> 4)] = make_float2(
                base[(size_t)(2 * f) * 256 + n] * scale,
                base[(size_t)(2 * f + 1) * 256 + n] * scale);
        }
    }
    __syncthreads();

    const int fl = t >> 4;
    const int r  = t & 15;
    float2 z[16];
    fft256_core(s, fl, r, z);       // z[k1] = Z[16k1 + r]
    __syncthreads();

    // Phase E: spectrum to smem at idx17(j), j = 16k1 + r -> 17k1 + r
    #pragma unroll
    for (int k1 = 0; k1 < 16; k1++)
        s[fl * PSTR + 17 * k1 + r] = z[k1];
    __syncthreads();

    // Phase F: conjugate untangle + transposed coalesced write of j=0..128
    for (int idx = t; idx < NJ * 16; idx += 128) {
        int j  = idx >> 4;
        int rr = idx & 15;
        int f  = rr >> 1;
        int jm = (256 - j) & 255;
        float2 zj = s[f * PSTR + j  + (j  >> 4)];
        float2 zm = s[f * PSTR + jm + (jm >> 4)];
        float2 v;
        if ((rr & 1) == 0)
            v = make_float2(0.5f * (zj.x + zm.x), 0.5f * (zj.y - zm.y));
        else
            v = make_float2(0.5f * (zj.y + zm.y), -0.5f * (zj.x - zm.x));
        g_scratch[((size_t)bc * NJ + j) * 256 + i0 + rr] = v;
    }
}

// ---------------------------------------------------------------------------
// Pass 2: column FFTs + magnitude + radial binning. 8 (bc,j) pairs per block.
// ---------------------------------------------------------------------------
__global__ void __launch_bounds__(128) colfft_kernel() {
    __shared__ float2 s[8 * PSTR];
    __shared__ unsigned char sb[8 * 256];

    const int t  = threadIdx.x;
    const int p0 = blockIdx.x * 8;

    // Phase A: load 8 columns (coalesced) + their bin rows
    #pragma unroll
    for (int l = 0; l < 16; l++) {
        int e = t + 128 * l;
        int f = e >> 8, n = e & 255;
        s[f * PSTR + n + (n >> 4)] = g_scratch[(size_t)(p0 + f) * 256 + n];
    }
    for (int l = t; l < 8 * 64; l += 128) {
        int f = l >> 6, w = l & 63;
        int j = (p0 + f) % NJ;
        ((unsigned int*)sb)[f * 64 + w] = ((const unsigned int*)g_bintab)[j * 64 + w];
    }
    __syncthreads();

    const int fl = t >> 4;
    const int k2 = t & 15;
    float2 z[16];
    fft256_core(s, fl, k2, z);      // z[k1] = X[16k1 + k2]

    // magnitude + binning (no spectrum round-trip)
    float bins[NBINS];
    #pragma unroll
    for (int k = 0; k < NBINS; k++) bins[k] = 0.0f;
    #pragma unroll
    for (int k1 = 0; k1 < 16; k1++) {
        float2 v = z[k1];
        float ss = fmaf(v.x, v.x, v.y * v.y);
        float mag = (ss > 0.0f) ? ss * rsqrtf(ss) : 0.0f;
        int b = sb[fl * 256 + 16 * k1 + k2];
        #pragma unroll
        for (int k = 0; k < NBINS; k++) bins[k] += (b == k) ? mag : 0.0f;
    }
    // reduce across the 16 lanes of this FFT (xor<16 stays in-group)
    #pragma unroll
    for (int k = 0; k < NBINS; k++) {
        #pragma unroll
        for (int o = 8; o > 0; o >>= 1)
            bins[k] += __shfl_xor_sync(0xffffffffu, bins[k], o);
    }
    if (k2 == 0) {
        int p = p0 + fl;
        int j = p % NJ;
        float mj = (j == 0 || j == 128) ? 1.0f : 2.0f;
        float* dst = g_partial + (size_t)p * NBINS;
        ((float4*)dst)[0] = make_float4(bins[0] * mj, bins[1] * mj, bins[2] * mj, bins[3] * mj);
        ((float4*)dst)[1] = make_float4(bins[4] * mj, bins[5] * mj, bins[6] * mj, bins[7] * mj);
    }
}

// ---------------------------------------------------------------------------
// Pass 3: per-batch reduce, mean over C, MLP + softmax + top-2 (unchanged).
// ---------------------------------------------------------------------------
__global__ void __launch_bounds__(256) finalize_kernel(
    const float* __restrict__ W1, const float* __restrict__ b1,
    const float* __restrict__ W2, const float* __restrict__ b2,
    float* __restrict__ outp, int out_size) {
    __shared__ float red[8 * NBINS];
    const int b = blockIdx.x;
    const int t = threadIdx.x;
    const float* base = g_partial + (size_t)b * 64 * NJ * NBINS;

    float bins[NBINS];
    #pragma unroll
    for (int k = 0; k < NBINS; k++) bins[k] = 0.0f;
    const int NU = 64 * NJ;
    for (int u = t; u < NU; u += 256) {
        const float4* p4 = (const float4*)(base + (size_t)u * NBINS);
        float4 lo = p4[0], hi = p4[1];
        bins[0] += lo.x; bins[1] += lo.y; bins[2] += lo.z; bins[3] += lo.w;
        bins[4] += hi.x; bins[5] += hi.y; bins[6] += hi.z; bins[7] += hi.w;
    }
    #pragma unroll
    for (int k = 0; k < NBINS; k++) {
        #pragma unroll
        for (int o = 16; o > 0; o >>= 1)
            bins[k] += __shfl_xor_sync(0xffffffffu, bins[k], o);
    }
    const int lane = t & 31, w = t >> 5;
    if (lane == 0) {
        #pragma unroll
        for (int k = 0; k < NBINS; k++) red[w * NBINS + k] = bins[k];
    }
    __syncthreads();

    if (t == 0) {
        float e[NBINS];
        #pragma unroll
        for (int k = 0; k < NBINS; k++) {
            float sum = 0.0f;
            #pragma unroll
            for (int ww = 0; ww < 8; ww++) sum += red[ww * NBINS + k];
            e[k] = sum * (1.0f / 64.0f);
        }
        float h[32];
        #pragma unroll
        for (int m = 0; m < 32; m++) {
            float acc = b1[m];
            #pragma unroll
            for (int k = 0; k < NBINS; k++) acc = fmaf(e[k], W1[m * NBINS + k], acc);
            h[m] = acc > 0.0f ? acc : 0.0f;
        }
        float lg[4];
        #pragma unroll
        for (int o = 0; o < 4; o++) {
            float acc = b2[o];
            #pragma unroll
            for (int m = 0; m < 32; m++) acc = fmaf(h[m], W2[o * 32 + m], acc);
            lg[o] = acc;
        }
        float mx = lg[0];
        #pragma unroll
        for (int o = 1; o < 4; o++) mx = fmaxf(mx, lg[o]);
        float ex[4], se = 0.0f;
        #pragma unroll
        for (int o = 0; o < 4; o++) { ex[o] = expf(lg[o] - mx); se += ex[o]; }
        float pr[4];
        #pragma unroll
        for (int o = 0; o < 4; o++) pr[o] = ex[o] / se;

        int i1 = 0;
        #pragma unroll
        for (int o = 1; o < 4; o++) if (pr[o] > pr[i1]) i1 = o;
        int i2 = -1;
        #pragma unroll
        for (int o = 0; o < 4; o++) {
            if (o == i1) continue;
            if (i2 < 0 || pr[o] > pr[i2]) i2 = o;
        }
        float q2 = expf(pr[i2] - pr[i1]);
        float w1v = 1.0f / (1.0f + q2);
        float w2v = q2 / (1.0f + q2);

        int o0 = b * 2, o1 = b * 2 + 1;
        if (o0 < out_size) outp[o0] = (float)i1;
        if (o1 < out_size) outp[o1] = (float)i2;
        if (32 + o0 < out_size) outp[32 + o0] = w1v;
        if (32 + o1 < out_size) outp[32 + o1] = w2v;
    }
}

// ---------------------------------------------------------------------------
extern "C" void kernel_launch(void* const* d_in, const int* in_sizes, int n_in,
                              void* d_out, int out_size) {
    const float* x  = (const float*)d_in[0];
    const float* W1 = (const float*)d_in[1];
    const float* b1 = (const float*)d_in[2];
    const float* W2 = (const float*)d_in[3];
    const float* b2 = (const float*)d_in[4];

    bintab_kernel<<<NJ, 256>>>();
    rowfft_kernel<<<BC * 16, 128>>>(x);
    colfft_kernel<<<(BC * NJ) / 8, 128>>>();   // 132096 / 8 = 16512
    finalize_kernel<<<16, 256>>>(W1, b1, W2, b2, (float*)d_out, out_size);
}